// round 2
// baseline (speedup 1.0000x reference)
#include <cuda_runtime.h>
#include <cuda_bf16.h>
#include <math.h>

#define D     512
#define KTOP  11          // 1 + K
#define KNEI  9           // reference uses idx[1:K] = 9 neighbors
#define NCLS  100
#define NB2   256
#define T2    256
#define NMAX  250000

// Scratch (allocation-free rule: __device__ globals)
__device__ float              g_scores[NMAX];
__device__ unsigned long long g_cand[NB2 * KTOP];

// ---- monotonic float key: bigger key == bigger value; tie -> smaller index wins ----
__device__ __forceinline__ unsigned long long make_key(float v, unsigned int idx) {
    unsigned int b = __float_as_uint(v);
    b = (b & 0x80000000u) ? ~b : (b | 0x80000000u);
    return ((unsigned long long)b << 32) | (unsigned int)(~idx);
}
__device__ __forceinline__ float key_val(unsigned long long k) {
    unsigned int o = (unsigned int)(k >> 32);
    unsigned int b = (o & 0x80000000u) ? (o ^ 0x80000000u) : ~o;
    return __uint_as_float(b);
}
__device__ __forceinline__ unsigned int key_idx(unsigned long long k) {
    return ~(unsigned int)(k & 0xFFFFFFFFu);
}

__device__ __forceinline__ unsigned long long block_max_u64(unsigned long long v,
                                                            unsigned long long* sh) {
    #pragma unroll
    for (int o = 16; o; o >>= 1) {
        unsigned long long u = __shfl_xor_sync(0xFFFFFFFFu, v, o);
        if (u > v) v = u;
    }
    int warp = threadIdx.x >> 5, lane = threadIdx.x & 31;
    if (lane == 0) sh[warp] = v;
    __syncthreads();
    if (warp == 0) {
        int nw = (blockDim.x + 31) >> 5;
        v = (lane < nw) ? sh[lane] : 0ULL;
        #pragma unroll
        for (int o = 4; o; o >>= 1) {
            unsigned long long u = __shfl_xor_sync(0xFFFFFFFFu, v, o);
            if (u > v) v = u;
        }
        if (lane == 0) sh[0] = v;
    }
    __syncthreads();
    unsigned long long r = sh[0];
    __syncthreads();
    return r;
}

// ---------- Kernel 1: fused dot + sumsq, warp-per-row, HBM-bound streaming ----------
__global__ void score_kernel(const float* __restrict__ coll,
                             const float* __restrict__ emb, int n) {
    __shared__ float4 sq[D / 4];
    int t = threadIdx.x;
    if (t < D / 4) sq[t] = reinterpret_cast<const float4*>(emb)[t];
    __syncthreads();

    int warp = t >> 5, lane = t & 31;
    int row = blockIdx.x * 8 + warp;
    if (row >= n) return;

    const float4* rp = reinterpret_cast<const float4*>(coll + (size_t)row * D);
    float dot = 0.f, rr = 0.f;
    #pragma unroll
    for (int j = 0; j < 4; j++) {
        float4 v = rp[lane + 32 * j];
        float4 q = sq[lane + 32 * j];
        dot += v.x * q.x + v.y * q.y + v.z * q.z + v.w * q.w;
        rr  += v.x * v.x + v.y * v.y + v.z * v.z + v.w * v.w;
    }
    #pragma unroll
    for (int o = 16; o; o >>= 1) {
        dot += __shfl_xor_sync(0xFFFFFFFFu, dot, o);
        rr  += __shfl_xor_sync(0xFFFFFFFFu, rr, o);
    }
    if (lane == 0)
        g_scores[row] = dot / sqrtf(rr + 1e-12f);   // q-norm scaling deferred (order-invariant)
}

// ---------- Kernel 2: per-block top-11 over 1MB of scores ----------
__global__ void topk_partial(int n) {
    __shared__ unsigned long long sh[33];
    unsigned long long keys[4];   // covers n <= 262144
    int base = blockIdx.x * T2 + threadIdx.x;
    #pragma unroll
    for (int j = 0; j < 4; j++) {
        int i = base + j * (NB2 * T2);
        keys[j] = (i < n) ? make_key(g_scores[i], (unsigned)i) : 0ULL;
    }
    for (int r = 0; r < KTOP; r++) {
        unsigned long long m = keys[0];
        if (keys[1] > m) m = keys[1];
        if (keys[2] > m) m = keys[2];
        if (keys[3] > m) m = keys[3];
        unsigned long long w = block_max_u64(m, sh);
        if (threadIdx.x == 0) g_cand[blockIdx.x * KTOP + r] = w;
        #pragma unroll
        for (int j = 0; j < 4; j++)
            if (keys[j] == w) keys[j] = 0ULL;   // keys unique (index embedded)
    }
}

// ---------- Kernel 3: merge 2816 candidates, vote, write output ----------
__global__ void finalize(const float* __restrict__ emb,
                         const int* __restrict__ labels,
                         float* __restrict__ out, int out_size) {
    __shared__ unsigned long long sh[33];
    __shared__ unsigned long long top[KTOP];
    __shared__ float sred[8];

    unsigned long long keys[KTOP];
    #pragma unroll
    for (int j = 0; j < KTOP; j++) {
        int i = threadIdx.x * KTOP + j;
        keys[j] = (i < NB2 * KTOP) ? g_cand[i] : 0ULL;
    }
    for (int r = 0; r < KTOP; r++) {
        unsigned long long m = 0ULL;
        #pragma unroll
        for (int j = 0; j < KTOP; j++)
            if (keys[j] > m) m = keys[j];
        unsigned long long w = block_max_u64(m, sh);
        if (threadIdx.x == 0) top[r] = w;
        #pragma unroll
        for (int j = 0; j < KTOP; j++)
            if (keys[j] == w) keys[j] = 0ULL;
    }

    // ||q||^2
    float q0 = emb[threadIdx.x], q1 = emb[threadIdx.x + 256];
    float s = q0 * q0 + q1 * q1;
    #pragma unroll
    for (int o = 16; o; o >>= 1) s += __shfl_xor_sync(0xFFFFFFFFu, s, o);
    if ((threadIdx.x & 31) == 0) sred[threadIdx.x >> 5] = s;
    __syncthreads();

    if (threadIdx.x == 0) {
        float qq = 0.f;
        #pragma unroll
        for (int w = 0; w < 8; w++) qq += sred[w];
        float inv_q = 1.0f / sqrtf(qq + 1e-12f);

        float vals[KTOP]; int idxs[KTOP];
        #pragma unroll
        for (int i = 0; i < KTOP; i++) {
            vals[i] = key_val(top[i]) * inv_q;
            idxs[i] = (int)key_idx(top[i]);
        }
        int preds[KNEI];
        #pragma unroll
        for (int j = 0; j < KNEI; j++) preds[j] = labels[idxs[1 + j]];

        int counts[NCLS];
        #pragma unroll
        for (int c = 0; c < NCLS; c++) counts[c] = 0;
        #pragma unroll
        for (int j = 0; j < KNEI; j++) {
            int p = preds[j];
            if (p >= 0 && p < NCLS) counts[p]++;
        }
        int best = 0;
        for (int c = 1; c < NCLS; c++)
            if (counts[c] > counts[best]) best = c;   // first-occurrence argmax
        int pos = 0;
        for (int j = KNEI - 1; j >= 0; j--)
            if (preds[j] == best) pos = j;            // first match
        float conf = vals[1 + pos];

        int m = out_size < KTOP ? out_size : KTOP;
        for (int i = 0; i < m; i++) out[i] = vals[i];
        if (out_size > KTOP)     out[KTOP]     = (float)best;
        if (out_size > KTOP + 1) out[KTOP + 1] = conf;
        for (int i = KTOP + 2; i < out_size; i++) out[i] = 0.0f;
    }
}

extern "C" void kernel_launch(void* const* d_in, const int* in_sizes, int n_in,
                              void* d_out, int out_size) {
    const float* emb    = (const float*)d_in[0];
    const float* coll   = (const float*)d_in[1];
    const int*   labels = (const int*)d_in[2];   // jnp.int64 canonicalizes to int32 (no x64)
    int n = in_sizes[1] / D;   // 250000

    score_kernel<<<(n + 7) / 8, 256>>>(coll, emb, n);
    topk_partial<<<NB2, T2>>>(n);
    finalize<<<1, 256>>>(emb, labels, (float*)d_out, out_size);
}